// round 7
// baseline (speedup 1.0000x reference)
#include <cuda_runtime.h>

#define BQ    16384
#define DIN   1024
#define DOUT  1024
#define HDIM  2048
#define NE    8
#define NA    (BQ*2)
#define PADM  35072              /* segments padded to 256 */
#define MB    (PADM/128)         /* 274 M-blocks of 128 rows */
#define KB1   (DIN/32)           /* 32 */
#define KB2   (HDIM/32)          /* 64 */
#define NT1   (HDIM/128)         /* 16 */
#define NT2   (DOUT/128)         /* 8  */
#define STAGE_UINTS 4096         /* 16KB: Ah 4K | Al 4K | Bh 4K | Bl 4K bytes */
#define DSMEM_BYTES (4*STAGE_UINTS*4)   /* 65536 */
#define QMAX  32512
#define SH    (8.0f/32512.0f)
#define SHI   (32512.0f/8.0f)

/* ------------- scratch: int8 hi/lo planes, fragment-blocked ---------------- */
/* A-block (128 rows x 32 k, int8) = 1024 uints: [mi(8)][lane(32)][4 uints]    */
/*   uint4 per lane = IMMA a-frag {a0,a1,a2,a3}                                */
/* B-block (128 cols x 32 k, int8) = 1024 uints: [ni(16)][lane(32)][2 uints]   */
__device__ __align__(256) unsigned g_xh[(size_t)PADM * DIN / 4];
__device__ __align__(256) unsigned g_xl[(size_t)PADM * DIN / 4];
__device__ __align__(256) unsigned g_w1h[(size_t)NE * HDIM * DIN / 4];
__device__ __align__(256) unsigned g_w1l[(size_t)NE * HDIM * DIN / 4];
__device__ __align__(256) unsigned g_w2h[(size_t)NE * DOUT * HDIM / 4];
__device__ __align__(256) unsigned g_w2l[(size_t)NE * DOUT * HDIM / 4];
__device__ __align__(256) unsigned g_hh[(size_t)PADM * HDIM / 4];
__device__ __align__(256) unsigned g_hl[(size_t)PADM * HDIM / 4];
__device__ float g_sx[BQ], g_sxi[BQ];
__device__ float g_w1s[NE * HDIM], g_w1si[NE * HDIM];
__device__ float g_w2s[NE * DOUT], g_w2si[NE * DOUT];
__device__ int   g_tok[PADM];
__device__ float g_wgt[PADM];
__device__ int   g_counts[NE];
__device__ int   g_cnt2[NE];
__device__ int   g_segbase[NE + 1];
__device__ int   g_tope[NA];
__device__ float g_topw[NA];
__device__ float g_probs_scratch[BQ * NE];

/* ------------- helpers ----------------------------------------------------- */
__device__ __forceinline__ unsigned smem_u32(const void* p) {
    unsigned a;
    asm("{ .reg .u64 t; cvta.to.shared.u64 t, %1; cvt.u32.u64 %0, t; }" : "=r"(a) : "l"(p));
    return a;
}
#define CP16(dst, src) \
    asm volatile("cp.async.cg.shared.global [%0], [%1], 16;" :: "r"(dst), "l"(src) : "memory")
#define CP_COMMIT() asm volatile("cp.async.commit_group;" ::: "memory")

__device__ __forceinline__ void imma(int* c, const uint4 a, const uint2 b) {
    asm("mma.sync.aligned.m16n8k32.row.col.s32.s8.s8.s32 "
        "{%0,%1,%2,%3}, {%4,%5,%6,%7}, {%8,%9}, {%0,%1,%2,%3};"
        : "+r"(c[0]), "+r"(c[1]), "+r"(c[2]), "+r"(c[3])
        : "r"(a.x), "r"(a.y), "r"(a.z), "r"(a.w), "r"(b.x), "r"(b.y));
}

/* quantize 4 floats -> int16 = hi*256+lo, pack hi/lo int8 quads */
__device__ __forceinline__ void q4(float4 v, float inv, unsigned& hi, unsigned& lo) {
    int X0 = max(-QMAX, min(QMAX, __float2int_rn(v.x * inv)));
    int X1 = max(-QMAX, min(QMAX, __float2int_rn(v.y * inv)));
    int X2 = max(-QMAX, min(QMAX, __float2int_rn(v.z * inv)));
    int X3 = max(-QMAX, min(QMAX, __float2int_rn(v.w * inv)));
    int h0 = (X0 + 128) >> 8, h1 = (X1 + 128) >> 8, h2 = (X2 + 128) >> 8, h3 = (X3 + 128) >> 8;
    int l0 = X0 - (h0 << 8), l1 = X1 - (h1 << 8), l2 = X2 - (h2 << 8), l3 = X3 - (h3 << 8);
    hi = (h0 & 255) | ((h1 & 255) << 8) | ((h2 & 255) << 16) | ((h3 & 255) << 24);
    lo = (l0 & 255) | ((l1 & 255) << 8) | ((l2 & 255) << 16) | ((l3 & 255) << 24);
}
/* quantize scalar -> (hi,lo) bytes */
__device__ __forceinline__ void q1(float v, float inv, int& h, int& l) {
    int X = max(-QMAX, min(QMAX, __float2int_rn(v * inv)));
    h = (X + 128) >> 8;
    l = X - (h << 8);
}

/* ------------- init --------------------------------------------------------- */
__global__ void k_zero_out(float* __restrict__ out) {
    size_t i = (size_t)blockIdx.x * blockDim.x + threadIdx.x;
    ((float4*)out)[i] = make_float4(0.f, 0.f, 0.f, 0.f);
}
__global__ void k_init() {
    int tid = threadIdx.x;
    if (tid < NE) { g_counts[tid] = 0; g_cnt2[tid] = 0; }
    for (int i = tid; i < PADM; i += blockDim.x) g_tok[i] = -1;
}

/* ------------- router (+ per-token amax for quantization) ------------------ */
__global__ void k_router(const float* __restrict__ x,
                         const float* __restrict__ rW,
                         const float* __restrict__ rb,
                         float* __restrict__ probs_out) {
    const int b = blockIdx.x;
    const int tid = threadIdx.x;
    const float* xr = x + (size_t)b * DIN;
    float acc[NE];
#pragma unroll
    for (int e = 0; e < NE; e++) acc[e] = 0.f;
    float amax = 0.f;
    for (int k = tid; k < DIN; k += 128) {
        float xv = xr[k];
        amax = fmaxf(amax, fabsf(xv));
#pragma unroll
        for (int e = 0; e < NE; e++) acc[e] = fmaf(xv, rW[e * DIN + k], acc[e]);
    }
    __shared__ float red[NE][128];
    __shared__ float rmx[128];
#pragma unroll
    for (int e = 0; e < NE; e++) red[e][tid] = acc[e];
    rmx[tid] = amax;
    __syncthreads();
    for (int s = 64; s > 0; s >>= 1) {
        if (tid < s) {
#pragma unroll
            for (int e = 0; e < NE; e++) red[e][tid] += red[e][tid + s];
            rmx[tid] = fmaxf(rmx[tid], rmx[tid + s]);
        }
        __syncthreads();
    }
    if (tid == 0) {
        float m = fmaxf(rmx[0], 1e-20f);
        g_sx[b] = m / (float)QMAX;
        g_sxi[b] = (float)QMAX / m;
        float lg[NE], mx = -1e30f;
#pragma unroll
        for (int e = 0; e < NE; e++) { lg[e] = red[e][0] + rb[e]; mx = fmaxf(mx, lg[e]); }
        float p[NE], s = 0.f;
#pragma unroll
        for (int e = 0; e < NE; e++) { p[e] = expf(lg[e] - mx); s += p[e]; }
        float inv = 1.f / s;
#pragma unroll
        for (int e = 0; e < NE; e++) { p[e] *= inv; probs_out[(size_t)b * NE + e] = p[e]; }
        int i0 = 0;
#pragma unroll
        for (int e = 1; e < NE; e++) if (p[e] > p[i0]) i0 = e;
        int i1 = (i0 == 0) ? 1 : 0;
#pragma unroll
        for (int e = 0; e < NE; e++) if (e != i0 && p[e] > p[i1]) i1 = e;
        float ws = p[i0] + p[i1];
        g_tope[2 * b]     = i0; g_topw[2 * b]     = p[i0] / ws;
        g_tope[2 * b + 1] = i1; g_topw[2 * b + 1] = p[i1] / ws;
        atomicAdd(&g_counts[i0], 1);
        atomicAdd(&g_counts[i1], 1);
    }
}

__global__ void k_prefix() {
    int base = 0;
    for (int e = 0; e < NE; e++) {
        g_segbase[e] = base;
        base += ((g_counts[e] + 255) >> 8) << 8;
    }
    g_segbase[NE] = base;
}
__global__ void k_scatter() {
    int a = blockIdx.x * 256 + threadIdx.x;
    if (a < NA) {
        int e = g_tope[a];
        int pos = g_segbase[e] + atomicAdd(&g_cnt2[e], 1);
        g_tok[pos] = a >> 1;
        g_wgt[pos] = g_topw[a];
    }
}

/* ------------- per-row amax of a weight matrix ----------------------------- */
__global__ void k_rowmax(const float* __restrict__ W, int Kdim,
                         float* __restrict__ sc, float* __restrict__ sci) {
    const int row = blockIdx.x;
    const int tid = threadIdx.x;
    const float* src = W + (size_t)row * Kdim;
    float amax = 0.f;
    for (int k = tid; k < Kdim; k += 256) amax = fmaxf(amax, fabsf(src[k]));
    __shared__ float rmx[256];
    rmx[tid] = amax;
    __syncthreads();
    for (int s = 128; s > 0; s >>= 1) {
        if (tid < s) rmx[tid] = fmaxf(rmx[tid], rmx[tid + s]);
        __syncthreads();
    }
    if (tid == 0) {
        float m = fmaxf(rmx[0], 1e-20f);
        sc[row] = m / (float)QMAX;
        sci[row] = (float)QMAX / m;
    }
}

/* ------------- x: gather + int16-split into A-layout ----------------------- */
__global__ void k_xsplit8(const float* __restrict__ x) {
    const int kb = blockIdx.x, mb = blockIdx.y;
    const int tid = threadIdx.x;                 /* 256 */
    const int lane = tid & 31, mi = tid >> 5;    /* mi 0..7 */
    const int g = lane >> 2, tig = lane & 3;
    const int r0 = mb * 128 + mi * 16 + g;
    const int t0 = g_tok[r0], t1 = g_tok[r0 + 8];
    const float i0 = (t0 >= 0) ? g_sxi[t0] : 0.f;
    const float i1 = (t1 >= 0) ? g_sxi[t1] : 0.f;
    const int col = kb * 32 + 4 * tig;
    float4 z = make_float4(0.f, 0.f, 0.f, 0.f);
    float4 v00 = z, v02 = z, v10 = z, v12 = z;
    if (t0 >= 0) {
        v00 = *(const float4*)&x[(size_t)t0 * DIN + col];
        v02 = *(const float4*)&x[(size_t)t0 * DIN + col + 16];
    }
    if (t1 >= 0) {
        v10 = *(const float4*)&x[(size_t)t1 * DIN + col];
        v12 = *(const float4*)&x[(size_t)t1 * DIN + col + 16];
    }
    uint4 H, L;
    q4(v00, i0, H.x, L.x);   /* a0: row g,   k..k+3   */
    q4(v10, i1, H.y, L.y);   /* a1: row g+8           */
    q4(v02, i0, H.z, L.z);   /* a2: row g,   k+16..   */
    q4(v12, i1, H.w, L.w);   /* a3: row g+8, k+16..   */
    const size_t base = ((size_t)mb * KB1 + kb) * 1024 + (size_t)tid * 4;
    *(uint4*)&g_xh[base] = H;
    *(uint4*)&g_xl[base] = L;
}

/* ------------- W: int16-split into B-layout -------------------------------- */
__global__ void k_wsplit8(const float* __restrict__ W, const float* __restrict__ sci,
                          unsigned* __restrict__ Gh, unsigned* __restrict__ Gl,
                          int Kdim) {
    const int kb = blockIdx.x, nt = blockIdx.y, e = blockIdx.z;
    const int NB = gridDim.y;
    const int tid = threadIdx.x;                 /* 512 */
    const int lane = tid & 31, ni = tid >> 5;    /* ni 0..15 */
    const int g = lane >> 2, tig = lane & 3;
    const size_t nrow = (size_t)e * (NB * 128) + nt * 128 + ni * 8 + g;
    const float inv = sci[nrow];
    const float* src = W + nrow * Kdim + kb * 32 + 4 * tig;
    float4 v0 = *(const float4*)src;
    float4 v1 = *(const float4*)(src + 16);
    uint2 H, L;
    q4(v0, inv, H.x, L.x);   /* b0: k..k+3,  col g */
    q4(v1, inv, H.y, L.y);   /* b1: k+16..,  col g */
    const size_t base = (((size_t)e * NB + nt) * (Kdim / 32) + kb) * 1024 + (size_t)tid * 2;
    *(uint2*)&Gh[base] = H;
    *(uint2*)&Gl[base] = L;
}

/* ------------- stage loader: 16KB via cp.async (4 x 16B per thread) -------- */
__device__ __forceinline__ void stage_load8(
    unsigned* smbuf, int st,
    const unsigned* __restrict__ Ah, const unsigned* __restrict__ Al,
    const unsigned* __restrict__ Bh, const unsigned* __restrict__ Bl,
    size_t ablk, size_t bblk, int tid)
{
    unsigned d = smem_u32(smbuf + st * STAGE_UINTS) + tid * 16;
    CP16(d,          Ah + ablk * 1024 + tid * 4);
    CP16(d + 4096u,  Al + ablk * 1024 + tid * 4);
    CP16(d + 8192u,  Bh + bblk * 1024 + tid * 4);
    CP16(d + 12288u, Bl + bblk * 1024 + tid * 4);
    CP_COMMIT();
}

/* ------------- IMMA mainloop (CTA 128x128, Kblk 32, 4 stages) -------------- */
__device__ __forceinline__ void gemm_loop8(
    unsigned* smbuf,
    const unsigned* __restrict__ Ah, const unsigned* __restrict__ Al,
    const unsigned* __restrict__ Bh, const unsigned* __restrict__ Bl,
    size_t ablk0, size_t bblk0, int KB,
    int accH[2][8][4], int accC[2][8][4], int tid)
{
    const int lane = tid & 31, wid = tid >> 5;
    const int wm = wid >> 1, wn = wid & 1;

#pragma unroll
    for (int s = 0; s < 3; s++)
        stage_load8(smbuf, s, Ah, Al, Bh, Bl, ablk0 + s, bblk0 + s, tid);

    for (int kb = 0; kb < KB; kb++) {
        const int st = kb & 3;
        if (kb + 3 < KB) {
            stage_load8(smbuf, (kb + 3) & 3, Ah, Al, Bh, Bl,
                        ablk0 + kb + 3, bblk0 + kb + 3, tid);
            asm volatile("cp.async.wait_group 3;" ::: "memory");
        } else {
            asm volatile("cp.async.wait_group 0;" ::: "memory");
        }
        __syncthreads();
        const unsigned* sA = smbuf + st * STAGE_UINTS;
        uint4 ah[2], al[2];
        uint2 bh[8], bl[8];
#pragma unroll
        for (int mi = 0; mi < 2; mi++) {
            ah[mi] = *(const uint4*)(sA + ((wm * 2 + mi) * 32 + lane) * 4);
            al[mi] = *(const uint4*)(sA + 1024 + ((wm * 2 + mi) * 32 + lane) * 4);
        }
#pragma unroll
        for (int j = 0; j < 8; j++) {
            bh[j] = *(const uint2*)(sA + 2048 + ((wn * 8 + j) * 32 + lane) * 2);
            bl[j] = *(const uint2*)(sA + 3072 + ((wn * 8 + j) * 32 + lane) * 2);
        }
#pragma unroll
        for (int mi = 0; mi < 2; mi++)
#pragma unroll
            for (int j = 0; j < 8; j++) {
                imma(accH[mi][j], ah[mi], bh[j]);
                imma(accC[mi][j], al[mi], bh[j]);
                imma(accC[mi][j], ah[mi], bl[j]);
            }
        __syncthreads();
    }
}

__device__ __forceinline__ int resolve_expert(int p0) {
    int e = -1;
    if (p0 < g_segbase[NE]) {
#pragma unroll
        for (int i = NE - 1; i >= 0; i--)
            if (p0 >= g_segbase[i]) { e = i; break; }
    }
    return e;
}

/* ------------- GEMM1: h = relu(X W1^T + b1) -> int16-split A-layout -------- */
__global__ __launch_bounds__(256, 1)
void k_gemm1(const float* __restrict__ b1) {
    __shared__ int s_e;
    __shared__ float ssx[128];
    extern __shared__ unsigned smbuf[];
    const int tid = threadIdx.x;
    const int nt = blockIdx.x, mt = blockIdx.y;

    if (tid == 0) s_e = resolve_expert(mt * 128);
    __syncthreads();
    const int e = s_e;
    if (e < 0) return;
    if (tid < 128) {
        int t = g_tok[mt * 128 + tid];
        ssx[tid] = (t >= 0) ? g_sx[t] : 0.f;
    }
    __syncthreads();

    int accH[2][8][4], accC[2][8][4];
#pragma unroll
    for (int i = 0; i < 2; i++)
#pragma unroll
        for (int j = 0; j < 8; j++)
#pragma unroll
            for (int c = 0; c < 4; c++) { accH[i][j][c] = 0; accC[i][j][c] = 0; }

    gemm_loop8(smbuf, g_xh, g_xl, g_w1h, g_w1l,
               (size_t)mt * KB1, ((size_t)e * NT1 + nt) * KB1, KB1, accH, accC, tid);

    /* epilogue: scale + bias + relu, int16 quantize (fixed scale 8/32512),
       stage bytes in smem, then write GEMM2 A-layout */
    const int lane = tid & 31, wid = tid >> 5;
    const int wm = wid >> 1, wn = wid & 1;
    const int g = lane >> 2, tig = lane & 3;
    char* stgh = (char*)smbuf;                /* 128 x pitch132 int8 */
    char* stgl = stgh + 16896;
    const float* w1s = g_w1s + (size_t)e * HDIM + nt * 128;
    const float* bb  = b1 + (size_t)e * HDIM + nt * 128;
#pragma unroll
    for (int mi = 0; mi < 2; mi++) {
        const int r0 = wm * 32 + mi * 16 + g;
        const float sA0 = ssx[r0], sA1 = ssx[r0 + 8];
#pragma unroll
        for (int j = 0; j < 8; j++) {
            const int c = wn * 64 + j * 8 + 2 * tig;
            const float wsx = w1s[c], wsy = w1s[c + 1];
            const float bx = bb[c], by = bb[c + 1];
            float v0 = fmaxf(fmaf(sA0 * wsx, 65536.f * (float)accH[mi][j][0] + 256.f * (float)accC[mi][j][0], bx), 0.f);
            float v1 = fmaxf(fmaf(sA0 * wsy, 65536.f * (float)accH[mi][j][1] + 256.f * (float)accC[mi][j][1], by), 0.f);
            float v2 = fmaxf(fmaf(sA1 * wsx, 65536.f * (float)accH[mi][j][2] + 256.f * (float)accC[mi][j][2], bx), 0.f);
            float v3 = fmaxf(fmaf(sA1 * wsy, 65536.f * (float)accH[mi][j][3] + 256.f * (float)accC[mi][j][3], by), 0.f);
            int h0, l0, h1, l1, h2, l2, h3, l3;
            q1(v0, SHI, h0, l0); q1(v1, SHI, h1, l1);
            q1(v2, SHI, h2, l2); q1(v3, SHI, h3, l3);
            *(unsigned short*)(stgh + r0 * 132 + c)       = (unsigned short)((h0 & 255) | ((h1 & 255) << 8));
            *(unsigned short*)(stgh + (r0 + 8) * 132 + c) = (unsigned short)((h2 & 255) | ((h3 & 255) << 8));
            *(unsigned short*)(stgl + r0 * 132 + c)       = (unsigned short)((l0 & 255) | ((l1 & 255) << 8));
            *(unsigned short*)(stgl + (r0 + 8) * 132 + c) = (unsigned short)((l2 & 255) | ((l3 & 255) << 8));
        }
    }
    __syncthreads();
    const int m8 = tid >> 5;
#pragma unroll
    for (int kbl = 0; kbl < 4; kbl++) {
        const int off = (m8 * 16 + g) * 132 + kbl * 32 + 4 * tig;
        uint4 H, L;
        H.x = *(unsigned*)(stgh + off);
        H.y = *(unsigned*)(stgh + off + 8 * 132);
        H.z = *(unsigned*)(stgh + off + 16);
        H.w = *(unsigned*)(stgh + off + 8 * 132 + 16);
        L.x = *(unsigned*)(stgl + off);
        L.y = *(unsigned*)(stgl + off + 8 * 132);
        L.z = *(unsigned*)(stgl + off + 16);
        L.w = *(unsigned*)(stgl + off + 8 * 132 + 16);
        const size_t base = ((size_t)mt * KB2 + nt * 4 + kbl) * 1024 + (size_t)tid * 4;
        *(uint4*)&g_hh[base] = H;
        *(uint4*)&g_hl[base] = L;
    }
}

/* ------------- GEMM2: out += w * (h W2^T + b2) ------------------------------ */
__global__ __launch_bounds__(256, 1)
void k_gemm2(const float* __restrict__ b2, float* __restrict__ out) {
    __shared__ int s_e;
    __shared__ int stok[128];
    __shared__ float swgt[128];
    extern __shared__ unsigned smbuf[];
    const int tid = threadIdx.x;
    const int nt = blockIdx.x, mt = blockIdx.y;

    if (tid == 0) s_e = resolve_expert(mt * 128);
    __syncthreads();
    const int e = s_e;
    if (e < 0) return;
    if (tid < 128) {
        stok[tid] = g_tok[mt * 128 + tid];
        swgt[tid] = g_wgt[mt * 128 + tid];
    }
    __syncthreads();

    int accH[2][8][4], accC[2][8][4];
#pragma unroll
    for (int i = 0; i < 2; i++)
#pragma unroll
        for (int j = 0; j < 8; j++)
#pragma unroll
            for (int c = 0; c < 4; c++) { accH[i][j][c] = 0; accC[i][j][c] = 0; }

    gemm_loop8(smbuf, g_hh, g_hl, g_w2h, g_w2l,
               (size_t)mt * KB2, ((size_t)e * NT2 + nt) * KB2, KB2, accH, accC, tid);

    const int lane = tid & 31, wid = tid >> 5;
    const int wm = wid >> 1, wn = wid & 1;
    const int g = lane >> 2, tig = lane & 3;
    const float* w2s = g_w2s + (size_t)e * DOUT + nt * 128;
    const float* bb  = b2 + (size_t)e * DOUT + nt * 128;
#pragma unroll
    for (int mi = 0; mi < 2; mi++) {
        const int r0 = wm * 32 + mi * 16 + g;
        const int t0 = stok[r0], t1 = stok[r0 + 8];
        const float w0 = swgt[r0], w1v = swgt[r0 + 8];
#pragma unroll
        for (int j = 0; j < 8; j++) {
            const int c = wn * 64 + j * 8 + 2 * tig;
            const float sx = SH * w2s[c], sy = SH * w2s[c + 1];
            const float bx = bb[c], by = bb[c + 1];
            const int colg = nt * 128 + c;
            if (t0 >= 0) {
                float f0 = fmaf(sx, 65536.f * (float)accH[mi][j][0] + 256.f * (float)accC[mi][j][0], bx);
                float f1 = fmaf(sy, 65536.f * (float)accH[mi][j][1] + 256.f * (float)accC[mi][j][1], by);
                float* d = out + (size_t)t0 * DOUT + colg;
                atomicAdd(d,     w0 * f0);
                atomicAdd(d + 1, w0 * f1);
            }
            if (t1 >= 0) {
                float f2 = fmaf(sx, 65536.f * (float)accH[mi][j][2] + 256.f * (float)accC[mi][j][2], bx);
                float f3 = fmaf(sy, 65536.f * (float)accH[mi][j][3] + 256.f * (float)accC[mi][j][3], by);
                float* d = out + (size_t)t1 * DOUT + colg;
                atomicAdd(d,     w1v * f2);
                atomicAdd(d + 1, w1v * f3);
            }
        }
    }
}

/* ------------- launch -------------------------------------------------------- */
extern "C" void kernel_launch(void* const* d_in, const int* in_sizes, int n_in,
                              void* d_out, int out_size) {
    const float* x  = (const float*)d_in[0];
    const float* rW = (const float*)d_in[1];
    const float* rb = (const float*)d_in[2];
    const float* W1 = (const float*)d_in[3];
    const float* b1 = (const float*)d_in[4];
    const float* W2 = (const float*)d_in[5];
    const float* b2 = (const float*)d_in[6];
    float* out = (float*)d_out;

    float* probs;
    if (out_size >= (int)(BQ * DOUT + BQ * NE)) {
        probs = out + (size_t)BQ * DOUT;
    } else {
        void* p = nullptr;
        cudaGetSymbolAddress(&p, g_probs_scratch);
        probs = (float*)p;
    }

    /* resolve DEVICE addresses for every scratch pointer passed as an arg
       (host-shadow symbol addresses silently write host RAM via ATS!) */
    void *p_w1h, *p_w1l, *p_w2h, *p_w2l, *p_w1s, *p_w1si, *p_w2s, *p_w2si;
    cudaGetSymbolAddress(&p_w1h, g_w1h);   cudaGetSymbolAddress(&p_w1l, g_w1l);
    cudaGetSymbolAddress(&p_w2h, g_w2h);   cudaGetSymbolAddress(&p_w2l, g_w2l);
    cudaGetSymbolAddress(&p_w1s, g_w1s);   cudaGetSymbolAddress(&p_w1si, g_w1si);
    cudaGetSymbolAddress(&p_w2s, g_w2s);   cudaGetSymbolAddress(&p_w2si, g_w2si);

    cudaFuncSetAttribute(k_gemm1, cudaFuncAttributeMaxDynamicSharedMemorySize, DSMEM_BYTES);
    cudaFuncSetAttribute(k_gemm2, cudaFuncAttributeMaxDynamicSharedMemorySize, DSMEM_BYTES);

    k_zero_out<<<16384, 256>>>(out);
    k_init<<<1, 256>>>();
    k_router<<<BQ, 128>>>(x, rW, rb, probs);
    k_prefix<<<1, 1>>>();
    k_scatter<<<NA / 256, 256>>>();
    k_rowmax<<<NE * HDIM, 256>>>(W1, DIN, (float*)p_w1s, (float*)p_w1si);
    k_rowmax<<<NE * DOUT, 256>>>(W2, HDIM, (float*)p_w2s, (float*)p_w2si);
    k_xsplit8<<<dim3(KB1, MB), 256>>>(x);
    k_wsplit8<<<dim3(KB1, NT1, NE), 512>>>(W1, (const float*)p_w1si,
                                           (unsigned*)p_w1h, (unsigned*)p_w1l, DIN);
    k_wsplit8<<<dim3(KB2, NT2, NE), 512>>>(W2, (const float*)p_w2si,
                                           (unsigned*)p_w2h, (unsigned*)p_w2l, HDIM);
    k_gemm1<<<dim3(NT1, MB), 256, DSMEM_BYTES>>>(b1);
    k_gemm2<<<dim3(NT2, MB), 256, DSMEM_BYTES>>>(b2, out);
    (void)in_sizes; (void)n_in;
}

// round 8
// speedup vs baseline: 6.4909x; 6.4909x over previous
#include <cuda_runtime.h>
#include <cuda_fp16.h>

#define BQ    16384
#define DIN   1024
#define DOUT  1024
#define HDIM  2048
#define NE    8
#define NA    (BQ*2)
#define PADM  35072              /* segments padded to 256: 137 blocks of 256 */
#define MT    137
#define KB1   (DIN/32)           /* 32 */
#define KB2   (HDIM/32)          /* 64 */
#define NT1   (HDIM/128)         /* 16 */
#define NT2   (DOUT/128)         /* 8  */
#define STAGE_UINTS 6144         /* 24KB: A 16KB | B 8KB */
#define DSMEM_BYTES (4*STAGE_UINTS*4)   /* 98304 */

/* ---------------- scratch: fp16 fragment-blocked buffers ------------------- */
/* A-block (256 rows x 32 k, fp16) = 4096 uints: [ki(2)][mi(16)][lane(32)][4]  */
/* B-block (128 cols x 32 k, fp16) = 2048 uints: [ki(2)][ni(16)][lane(32)][2]  */
__device__ __align__(256) unsigned g_xh[(size_t)PADM * DIN / 2];
__device__ __align__(256) unsigned g_w1h[(size_t)NE * HDIM * DIN / 2];
__device__ __align__(256) unsigned g_w2h[(size_t)NE * DOUT * HDIM / 2];
__device__ __align__(256) unsigned g_hh[(size_t)PADM * HDIM / 2];
__device__ int   g_tok[PADM];
__device__ float g_wgt[PADM];
__device__ int   g_counts[NE];
__device__ int   g_cnt2[NE];
__device__ int   g_segbase[NE + 1];
__device__ int   g_tope[NA];
__device__ float g_topw[NA];
__device__ float g_probs_scratch[BQ * NE];

/* ---------------- helpers -------------------------------------------------- */
__device__ __forceinline__ unsigned smem_u32(const void* p) {
    unsigned a;
    asm("{ .reg .u64 t; cvta.to.shared.u64 t, %1; cvt.u32.u64 %0, t; }" : "=r"(a) : "l"(p));
    return a;
}
#define CP16(dst, src) \
    asm volatile("cp.async.cg.shared.global [%0], [%1], 16;" :: "r"(dst), "l"(src) : "memory")
#define CP_COMMIT() asm volatile("cp.async.commit_group;" ::: "memory")

__device__ __forceinline__ void mma16816(float* c, const uint4 a, const uint2 b) {
    asm("mma.sync.aligned.m16n8k16.row.col.f32.f16.f16.f32 "
        "{%0,%1,%2,%3}, {%4,%5,%6,%7}, {%8,%9}, {%0,%1,%2,%3};"
        : "+f"(c[0]), "+f"(c[1]), "+f"(c[2]), "+f"(c[3])
        : "r"(a.x), "r"(a.y), "r"(a.z), "r"(a.w), "r"(b.x), "r"(b.y));
}
__device__ __forceinline__ unsigned pack2(float a, float b) {
    __half2 h = __floats2half2_rn(a, b);
    return *reinterpret_cast<unsigned*>(&h);
}

/* ---------------- init ------------------------------------------------------ */
__global__ void k_zero_out(float* __restrict__ out) {
    size_t i = (size_t)blockIdx.x * blockDim.x + threadIdx.x;
    ((float4*)out)[i] = make_float4(0.f, 0.f, 0.f, 0.f);
}
__global__ void k_init() {
    int tid = threadIdx.x;
    if (tid < NE) { g_counts[tid] = 0; g_cnt2[tid] = 0; }
    for (int i = tid; i < PADM; i += blockDim.x) g_tok[i] = -1;
}

/* ---------------- router ---------------------------------------------------- */
__global__ void k_router(const float* __restrict__ x,
                         const float* __restrict__ rW,
                         const float* __restrict__ rb,
                         float* __restrict__ probs_out) {
    const int b = blockIdx.x;
    const int tid = threadIdx.x;
    const float* xr = x + (size_t)b * DIN;
    float acc[NE];
#pragma unroll
    for (int e = 0; e < NE; e++) acc[e] = 0.f;
    for (int k = tid; k < DIN; k += 128) {
        float xv = xr[k];
#pragma unroll
        for (int e = 0; e < NE; e++) acc[e] = fmaf(xv, rW[e * DIN + k], acc[e]);
    }
    __shared__ float red[NE][128];
#pragma unroll
    for (int e = 0; e < NE; e++) red[e][tid] = acc[e];
    __syncthreads();
    for (int s = 64; s > 0; s >>= 1) {
        if (tid < s) {
#pragma unroll
            for (int e = 0; e < NE; e++) red[e][tid] += red[e][tid + s];
        }
        __syncthreads();
    }
    if (tid == 0) {
        float lg[NE], mx = -1e30f;
#pragma unroll
        for (int e = 0; e < NE; e++) { lg[e] = red[e][0] + rb[e]; mx = fmaxf(mx, lg[e]); }
        float p[NE], s = 0.f;
#pragma unroll
        for (int e = 0; e < NE; e++) { p[e] = expf(lg[e] - mx); s += p[e]; }
        float inv = 1.f / s;
#pragma unroll
        for (int e = 0; e < NE; e++) { p[e] *= inv; probs_out[(size_t)b * NE + e] = p[e]; }
        int i0 = 0;
#pragma unroll
        for (int e = 1; e < NE; e++) if (p[e] > p[i0]) i0 = e;
        int i1 = (i0 == 0) ? 1 : 0;
#pragma unroll
        for (int e = 0; e < NE; e++) if (e != i0 && p[e] > p[i1]) i1 = e;
        float ws = p[i0] + p[i1];
        g_tope[2 * b]     = i0; g_topw[2 * b]     = p[i0] / ws;
        g_tope[2 * b + 1] = i1; g_topw[2 * b + 1] = p[i1] / ws;
        atomicAdd(&g_counts[i0], 1);
        atomicAdd(&g_counts[i1], 1);
    }
}

__global__ void k_prefix() {
    int base = 0;
    for (int e = 0; e < NE; e++) {
        g_segbase[e] = base;
        base += ((g_counts[e] + 255) >> 8) << 8;
    }
    g_segbase[NE] = base;
}
__global__ void k_scatter() {
    int a = blockIdx.x * 256 + threadIdx.x;
    if (a < NA) {
        int e = g_tope[a];
        int pos = g_segbase[e] + atomicAdd(&g_cnt2[e], 1);
        g_tok[pos] = a >> 1;
        g_wgt[pos] = g_topw[a];
    }
}

/* ---------------- x: gather + fp16 convert into A-layout ------------------- */
__global__ void k_xsplit(const float* __restrict__ x) {
    const int kb = blockIdx.x, mb = blockIdx.y;
    const int tid = threadIdx.x;                 /* 512 */
    const int lane = tid & 31, mi = tid >> 5;
    const int g = lane >> 2, tig = lane & 3;
    const int row0 = mb * 256 + mi * 16 + g;
    const int t0 = g_tok[row0], t1 = g_tok[row0 + 8];
    const size_t blk = ((size_t)mb * KB1 + kb) * 4096;
#pragma unroll
    for (int ki = 0; ki < 2; ki++) {
        const int col = kb * 32 + ki * 16 + 2 * tig;
        float2 z = make_float2(0.f, 0.f);
        float2 v00 = z, v01 = z, v10 = z, v11 = z;
        if (t0 >= 0) {
            v00 = *(const float2*)&x[(size_t)t0 * DIN + col];
            v01 = *(const float2*)&x[(size_t)t0 * DIN + col + 8];
        }
        if (t1 >= 0) {
            v10 = *(const float2*)&x[(size_t)t1 * DIN + col];
            v11 = *(const float2*)&x[(size_t)t1 * DIN + col + 8];
        }
        uint4 H;
        H.x = pack2(v00.x, v00.y);   /* a0: (g,   c..c+1)   */
        H.y = pack2(v10.x, v10.y);   /* a1: (g+8, c..c+1)   */
        H.z = pack2(v01.x, v01.y);   /* a2: (g,   c+8..c+9) */
        H.w = pack2(v11.x, v11.y);   /* a3: (g+8, c+8..c+9) */
        *(uint4*)&g_xh[blk + ((size_t)(ki * 16 + mi) * 32 + lane) * 4] = H;
    }
}

/* ---------------- W: fp16 convert into B-layout ----------------------------- */
/* Gh must be a DEVICE address resolved via cudaGetSymbolAddress on host!      */
__global__ void k_wsplit(const float* __restrict__ W,
                         unsigned* __restrict__ Gh, int Kdim) {
    const int kb = blockIdx.x, nt = blockIdx.y, e = blockIdx.z;
    const int NB = gridDim.y;
    const int tid = threadIdx.x;                 /* 512 */
    const int lane = tid & 31, ni = tid >> 5;
    const int g = lane >> 2, tig = lane & 3;
    const size_t nrow = (size_t)e * (NB * 128) + nt * 128 + ni * 8 + g;
    const float* src = W + nrow * Kdim + kb * 32;
    const size_t blk = (((size_t)e * NB + nt) * (Kdim / 32) + kb) * 2048;
#pragma unroll
    for (int ki = 0; ki < 2; ki++) {
        const int k0 = ki * 16 + 2 * tig;
        float2 w0 = *(const float2*)&src[k0];
        float2 w1 = *(const float2*)&src[k0 + 8];
        uint2 H;
        H.x = pack2(w0.x, w0.y);     /* b0: k=2tig..+1      */
        H.y = pack2(w1.x, w1.y);     /* b1: k=2tig+8..+9    */
        *(uint2*)&Gh[blk + ((size_t)(ki * 16 + ni) * 32 + lane) * 2] = H;
    }
}

/* ---------------- stage loader: 24KB via cp.async (6 x 16B per thread) ----- */
__device__ __forceinline__ void stage_load(
    unsigned* smbuf, int st,
    const unsigned* __restrict__ Ah, const unsigned* __restrict__ Bh,
    size_t ablk, size_t bblk, int tid)
{
    unsigned d = smem_u32(smbuf + st * STAGE_UINTS) + tid * 16;
    const unsigned* a = Ah + ablk * 4096 + tid * 4;
    const unsigned* b = Bh + bblk * 2048 + tid * 4;
#pragma unroll
    for (int i = 0; i < 4; i++) CP16(d + i * 4096, a + i * 1024);
    CP16(d + 16384u, b);
    CP16(d + 20480u, b + 1024);
    CP_COMMIT();
}

/* ---------------- GEMM mainloop (CTA 256x128, Kblk 32, 4 stages) ----------- */
__device__ __forceinline__ void gemm_loop(
    unsigned* smbuf,
    const unsigned* __restrict__ Ah, const unsigned* __restrict__ Bh,
    size_t ablk0, size_t bblk0, int KB,
    float acc[4][8][4], int tid)
{
    const int lane = tid & 31, wid = tid >> 5;
    const int wm = wid >> 1, wn = wid & 1;

#pragma unroll
    for (int s = 0; s < 3; s++)
        stage_load(smbuf, s, Ah, Bh, ablk0 + s, bblk0 + s, tid);

    for (int kb = 0; kb < KB; kb++) {
        const int st = kb & 3;
        if (kb + 2 < KB) {
            asm volatile("cp.async.wait_group 2;" ::: "memory");
        } else {
            asm volatile("cp.async.wait_group 0;" ::: "memory");
        }
        __syncthreads();        /* stage kb ready; all warps done with kb-1 */
        const unsigned* sA = smbuf + st * STAGE_UINTS;
        const unsigned* sB = sA + 4096;
#pragma unroll
        for (int ki = 0; ki < 2; ki++) {
            const unsigned* pa = sA + ((ki * 16 + wm * 4) * 32 + lane) * 4;
            const unsigned* pb = sB + ((ki * 16 + wn * 8) * 32 + lane) * 2;
            uint4 ah[4];
            uint2 bh[8];
#pragma unroll
            for (int i = 0; i < 4; i++) ah[i] = *(const uint4*)(pa + i * 128);
#pragma unroll
            for (int j = 0; j < 8; j++) bh[j] = *(const uint2*)(pb + j * 64);
#pragma unroll
            for (int i = 0; i < 4; i++)
#pragma unroll
                for (int j = 0; j < 8; j++) mma16816(acc[i][j], ah[i], bh[j]);
        }
        if (kb + 3 < KB)
            stage_load(smbuf, (kb + 3) & 3, Ah, Bh, ablk0 + kb + 3, bblk0 + kb + 3, tid);
    }
}

__device__ __forceinline__ int resolve_expert(int p0) {
    int e = -1;
    if (p0 < g_segbase[NE]) {
#pragma unroll
        for (int i = NE - 1; i >= 0; i--)
            if (p0 >= g_segbase[i]) { e = i; break; }
    }
    return e;
}

/* ---------------- GEMM1: h = relu(X W1^T + b1) -> fp16 A-layout ------------- */
__global__ __launch_bounds__(256, 1)
void k_gemm1(const float* __restrict__ b1) {
    __shared__ int s_e;
    extern __shared__ unsigned smbuf[];
    const int tid = threadIdx.x;
    const int nt = blockIdx.x, mt = blockIdx.y;

    if (tid == 0) s_e = resolve_expert(mt * 256);
    __syncthreads();
    const int e = s_e;
    if (e < 0) return;

    float acc[4][8][4];
#pragma unroll
    for (int i = 0; i < 4; i++)
#pragma unroll
        for (int j = 0; j < 8; j++)
#pragma unroll
            for (int c = 0; c < 4; c++) acc[i][j][c] = 0.f;

    gemm_loop(smbuf, g_xh, g_w1h,
              (size_t)mt * KB1, ((size_t)e * NT1 + nt) * KB1, KB1, acc, tid);

    /* epilogue: bias+relu, fp16 convert, write h in A-layout (C-frag == A-frag) */
    const int lane = tid & 31, wid = tid >> 5;
    const int wm = wid >> 1, wn = wid & 1;
    const int tig = lane & 3;
    const float* bias = b1 + (size_t)e * HDIM + nt * 128 + wn * 64 + 2 * tig;
#pragma unroll
    for (int mi = 0; mi < 4; mi++) {
        const int mig = wm * 4 + mi;
#pragma unroll
        for (int jp = 0; jp < 4; jp++) {
            float2 b0 = *(const float2*)(bias + (2 * jp) * 8);
            float2 b1v = *(const float2*)(bias + (2 * jp + 1) * 8);
            const float* c0 = acc[mi][2 * jp];
            const float* c1 = acc[mi][2 * jp + 1];
            uint4 H;
            H.x = pack2(fmaxf(c0[0] + b0.x, 0.f),  fmaxf(c0[1] + b0.y, 0.f));
            H.y = pack2(fmaxf(c0[2] + b0.x, 0.f),  fmaxf(c0[3] + b0.y, 0.f));
            H.z = pack2(fmaxf(c1[0] + b1v.x, 0.f), fmaxf(c1[1] + b1v.y, 0.f));
            H.w = pack2(fmaxf(c1[2] + b1v.x, 0.f), fmaxf(c1[3] + b1v.y, 0.f));
            const int hcol0 = nt * 128 + wn * 64 + jp * 16;
            const size_t base = ((size_t)mt * KB2 + (hcol0 >> 5)) * 4096
                + ((size_t)(((hcol0 >> 4) & 1) * 16 + mig) * 32 + lane) * 4;
            *(uint4*)&g_hh[base] = H;
        }
    }
}

/* ---------------- GEMM2: out += w * (h W2^T + b2) --------------------------- */
__global__ __launch_bounds__(256, 1)
void k_gemm2(const float* __restrict__ b2, float* __restrict__ out) {
    __shared__ int s_e;
    __shared__ int stok[256];
    __shared__ float swgt[256];
    extern __shared__ unsigned smbuf[];
    const int tid = threadIdx.x;
    const int nt = blockIdx.x, mt = blockIdx.y;

    if (tid == 0) s_e = resolve_expert(mt * 256);
    __syncthreads();
    const int e = s_e;
    if (e < 0) return;

    stok[tid] = g_tok[mt * 256 + tid];
    swgt[tid] = g_wgt[mt * 256 + tid];

    float acc[4][8][4];
#pragma unroll
    for (int i = 0; i < 4; i++)
#pragma unroll
        for (int j = 0; j < 8; j++)
#pragma unroll
            for (int c = 0; c < 4; c++) acc[i][j][c] = 0.f;

    gemm_loop(smbuf, g_hh, g_w2h,
              (size_t)mt * KB2, ((size_t)e * NT2 + nt) * KB2, KB2, acc, tid);

    const int lane = tid & 31, wid = tid >> 5;
    const int wm = wid >> 1, wn = wid & 1;
    const int g = lane >> 2, tig = lane & 3;
#pragma unroll
    for (int mi = 0; mi < 4; mi++) {
        const int r0 = wm * 64 + mi * 16 + g;
        const int t0 = stok[r0], t1 = stok[r0 + 8];
        const float w0 = swgt[r0], w1 = swgt[r0 + 8];
#pragma unroll
        for (int j = 0; j < 8; j++) {
            const int col = nt * 128 + wn * 64 + j * 8 + 2 * tig;
            float2 bb = *(const float2*)&b2[(size_t)e * DOUT + col];
            if (t0 >= 0) {
                float* d = out + (size_t)t0 * DOUT + col;
                atomicAdd(d,     w0 * (acc[mi][j][0] + bb.x));
                atomicAdd(d + 1, w0 * (acc[mi][j][1] + bb.y));
            }
            if (t1 >= 0) {
                float* d = out + (size_t)t1 * DOUT + col;
                atomicAdd(d,     w1 * (acc[mi][j][2] + bb.x));
                atomicAdd(d + 1, w1 * (acc[mi][j][3] + bb.y));
            }
        }
    }
}

/* ---------------- launch ----------------------------------------------------- */
extern "C" void kernel_launch(void* const* d_in, const int* in_sizes, int n_in,
                              void* d_out, int out_size) {
    const float* x  = (const float*)d_in[0];
    const float* rW = (const float*)d_in[1];
    const float* rb = (const float*)d_in[2];
    const float* W1 = (const float*)d_in[3];
    const float* b1 = (const float*)d_in[4];
    const float* W2 = (const float*)d_in[5];
    const float* b2 = (const float*)d_in[6];
    float* out = (float*)d_out;

    float* probs;
    if (out_size >= (int)(BQ * DOUT + BQ * NE)) {
        probs = out + (size_t)BQ * DOUT;
    } else {
        void* p = nullptr;
        cudaGetSymbolAddress(&p, g_probs_scratch);
        probs = (float*)p;
    }

    /* resolve DEVICE addresses for scratch passed as kernel args (ATS trap!) */
    void *p_w1h = nullptr, *p_w2h = nullptr;
    cudaGetSymbolAddress(&p_w1h, g_w1h);
    cudaGetSymbolAddress(&p_w2h, g_w2h);

    cudaFuncSetAttribute(k_gemm1, cudaFuncAttributeMaxDynamicSharedMemorySize, DSMEM_BYTES);
    cudaFuncSetAttribute(k_gemm2, cudaFuncAttributeMaxDynamicSharedMemorySize, DSMEM_BYTES);

    k_zero_out<<<16384, 256>>>(out);
    k_init<<<1, 256>>>();
    k_router<<<BQ, 128>>>(x, rW, rb, probs);
    k_prefix<<<1, 1>>>();
    k_scatter<<<NA / 256, 256>>>();
    k_xsplit<<<dim3(KB1, MT), 512>>>(x);
    k_wsplit<<<dim3(KB1, NT1, NE), 512>>>(W1, (unsigned*)p_w1h, DIN);
    k_wsplit<<<dim3(KB2, NT2, NE), 512>>>(W2, (unsigned*)p_w2h, HDIM);
    k_gemm1<<<dim3(NT1, MT), 256, DSMEM_BYTES>>>(b1);
    k_gemm2<<<dim3(NT2, MT), 256, DSMEM_BYTES>>>(b2, out);
    (void)in_sizes; (void)n_in;
}

// round 9
// speedup vs baseline: 6.5733x; 1.0127x over previous
#include <cuda_runtime.h>
#include <cuda_fp16.h>

#define BQ    16384
#define DIN   1024
#define DOUT  1024
#define HDIM  2048
#define NE    8
#define NA    (BQ*2)
#define PADM  35072              /* segments padded to 256: 137 blocks of 256 */
#define MT    137
#define KB1   (DIN/32)           /* 32 */
#define KB2   (HDIM/32)          /* 64 */
#define NT1   (HDIM/128)         /* 16 */
#define NT2   (DOUT/128)         /* 8  */
#define STAGE_UINTS 6144         /* 24KB: A 16KB | B 8KB */
#define DSMEM_BYTES (4*STAGE_UINTS*4)   /* 98304 */

/* ---------------- scratch: fp16 fragment-blocked buffers ------------------- */
/* A-block (256 rows x 32 k, fp16) = 4096 uints: [ki(2)][mi(16)][lane(32)][4]  */
/* B-block (128 cols x 32 k, fp16) = 2048 uints: [ki(2)][ni(16)][lane(32)][2]  */
__device__ __align__(256) unsigned g_xh[(size_t)PADM * DIN / 2];
__device__ __align__(256) unsigned g_w1h[(size_t)NE * HDIM * DIN / 2];
__device__ __align__(256) unsigned g_w2h[(size_t)NE * DOUT * HDIM / 2];
__device__ __align__(256) unsigned g_hh[(size_t)PADM * HDIM / 2];
__device__ __align__(256) float    g_y[(size_t)PADM * DOUT];   /* per-slot weighted y */
__device__ int   g_tok[PADM];
__device__ float g_wgt[PADM];
__device__ int   g_slot[NA];     /* assignment -> padded slot row */
__device__ int   g_counts[NE];
__device__ int   g_cnt2[NE];
__device__ int   g_segbase[NE + 1];
__device__ int   g_tope[NA];
__device__ float g_topw[NA];
__device__ float g_probs_scratch[BQ * NE];

/* ---------------- helpers -------------------------------------------------- */
__device__ __forceinline__ unsigned smem_u32(const void* p) {
    unsigned a;
    asm("{ .reg .u64 t; cvta.to.shared.u64 t, %1; cvt.u32.u64 %0, t; }" : "=r"(a) : "l"(p));
    return a;
}
#define CP16(dst, src) \
    asm volatile("cp.async.cg.shared.global [%0], [%1], 16;" :: "r"(dst), "l"(src) : "memory")
#define CP_COMMIT() asm volatile("cp.async.commit_group;" ::: "memory")

__device__ __forceinline__ void mma16816(float* c, const uint4 a, const uint2 b) {
    asm("mma.sync.aligned.m16n8k16.row.col.f32.f16.f16.f32 "
        "{%0,%1,%2,%3}, {%4,%5,%6,%7}, {%8,%9}, {%0,%1,%2,%3};"
        : "+f"(c[0]), "+f"(c[1]), "+f"(c[2]), "+f"(c[3])
        : "r"(a.x), "r"(a.y), "r"(a.z), "r"(a.w), "r"(b.x), "r"(b.y));
}
__device__ __forceinline__ unsigned pack2(float a, float b) {
    __half2 h = __floats2half2_rn(a, b);
    return *reinterpret_cast<unsigned*>(&h);
}

/* ---------------- init ------------------------------------------------------ */
__global__ void k_init() {
    int i = blockIdx.x * blockDim.x + threadIdx.x;
    if (i < NE) { g_counts[i] = 0; g_cnt2[i] = 0; }
    if (i < PADM) g_tok[i] = -1;
}

/* ---------------- router ---------------------------------------------------- */
__global__ void k_router(const float* __restrict__ x,
                         const float* __restrict__ rW,
                         const float* __restrict__ rb,
                         float* __restrict__ probs_out) {
    const int b = blockIdx.x;
    const int tid = threadIdx.x;
    const float* xr = x + (size_t)b * DIN;
    float acc[NE];
#pragma unroll
    for (int e = 0; e < NE; e++) acc[e] = 0.f;
    for (int k = tid; k < DIN; k += 128) {
        float xv = xr[k];
#pragma unroll
        for (int e = 0; e < NE; e++) acc[e] = fmaf(xv, rW[e * DIN + k], acc[e]);
    }
    __shared__ float red[NE][128];
#pragma unroll
    for (int e = 0; e < NE; e++) red[e][tid] = acc[e];
    __syncthreads();
    for (int s = 64; s > 0; s >>= 1) {
        if (tid < s) {
#pragma unroll
            for (int e = 0; e < NE; e++) red[e][tid] += red[e][tid + s];
        }
        __syncthreads();
    }
    if (tid == 0) {
        float lg[NE], mx = -1e30f;
#pragma unroll
        for (int e = 0; e < NE; e++) { lg[e] = red[e][0] + rb[e]; mx = fmaxf(mx, lg[e]); }
        float p[NE], s = 0.f;
#pragma unroll
        for (int e = 0; e < NE; e++) { p[e] = expf(lg[e] - mx); s += p[e]; }
        float inv = 1.f / s;
#pragma unroll
        for (int e = 0; e < NE; e++) { p[e] *= inv; probs_out[(size_t)b * NE + e] = p[e]; }
        int i0 = 0;
#pragma unroll
        for (int e = 1; e < NE; e++) if (p[e] > p[i0]) i0 = e;
        int i1 = (i0 == 0) ? 1 : 0;
#pragma unroll
        for (int e = 0; e < NE; e++) if (e != i0 && p[e] > p[i1]) i1 = e;
        float ws = p[i0] + p[i1];
        g_tope[2 * b]     = i0; g_topw[2 * b]     = p[i0] / ws;
        g_tope[2 * b + 1] = i1; g_topw[2 * b + 1] = p[i1] / ws;
        atomicAdd(&g_counts[i0], 1);
        atomicAdd(&g_counts[i1], 1);
    }
}

__global__ void k_prefix() {
    int base = 0;
    for (int e = 0; e < NE; e++) {
        g_segbase[e] = base;
        base += ((g_counts[e] + 255) >> 8) << 8;
    }
    g_segbase[NE] = base;
}
__global__ void k_scatter() {
    int a = blockIdx.x * 256 + threadIdx.x;
    if (a < NA) {
        int e = g_tope[a];
        int pos = g_segbase[e] + atomicAdd(&g_cnt2[e], 1);
        g_tok[pos] = a >> 1;
        g_wgt[pos] = g_topw[a];
        g_slot[a] = pos;
    }
}

/* ---------------- x: gather + fp16 convert into A-layout ------------------- */
__global__ void k_xsplit(const float* __restrict__ x) {
    const int kb = blockIdx.x, mb = blockIdx.y;
    const int tid = threadIdx.x;                 /* 512 */
    const int lane = tid & 31, mi = tid >> 5;
    const int g = lane >> 2, tig = lane & 3;
    const int row0 = mb * 256 + mi * 16 + g;
    const int t0 = g_tok[row0], t1 = g_tok[row0 + 8];
    const size_t blk = ((size_t)mb * KB1 + kb) * 4096;
#pragma unroll
    for (int ki = 0; ki < 2; ki++) {
        const int col = kb * 32 + ki * 16 + 2 * tig;
        float2 z = make_float2(0.f, 0.f);
        float2 v00 = z, v01 = z, v10 = z, v11 = z;
        if (t0 >= 0) {
            v00 = *(const float2*)&x[(size_t)t0 * DIN + col];
            v01 = *(const float2*)&x[(size_t)t0 * DIN + col + 8];
        }
        if (t1 >= 0) {
            v10 = *(const float2*)&x[(size_t)t1 * DIN + col];
            v11 = *(const float2*)&x[(size_t)t1 * DIN + col + 8];
        }
        uint4 H;
        H.x = pack2(v00.x, v00.y);   /* a0: (g,   c..c+1)   */
        H.y = pack2(v10.x, v10.y);   /* a1: (g+8, c..c+1)   */
        H.z = pack2(v01.x, v01.y);   /* a2: (g,   c+8..c+9) */
        H.w = pack2(v11.x, v11.y);   /* a3: (g+8, c+8..c+9) */
        *(uint4*)&g_xh[blk + ((size_t)(ki * 16 + mi) * 32 + lane) * 4] = H;
    }
}

/* ---------------- W: fp16 convert into B-layout ----------------------------- */
/* Gh must be a DEVICE address resolved via cudaGetSymbolAddress on host!      */
__global__ void k_wsplit(const float* __restrict__ W,
                         unsigned* __restrict__ Gh, int Kdim) {
    const int kb = blockIdx.x, nt = blockIdx.y, e = blockIdx.z;
    const int NB = gridDim.y;
    const int tid = threadIdx.x;                 /* 512 */
    const int lane = tid & 31, ni = tid >> 5;
    const int g = lane >> 2, tig = lane & 3;
    const size_t nrow = (size_t)e * (NB * 128) + nt * 128 + ni * 8 + g;
    const float* src = W + nrow * Kdim + kb * 32;
    const size_t blk = (((size_t)e * NB + nt) * (Kdim / 32) + kb) * 2048;
#pragma unroll
    for (int ki = 0; ki < 2; ki++) {
        const int k0 = ki * 16 + 2 * tig;
        float2 w0 = *(const float2*)&src[k0];
        float2 w1 = *(const float2*)&src[k0 + 8];
        uint2 H;
        H.x = pack2(w0.x, w0.y);     /* b0: k=2tig..+1      */
        H.y = pack2(w1.x, w1.y);     /* b1: k=2tig+8..+9    */
        *(uint2*)&Gh[blk + ((size_t)(ki * 16 + ni) * 32 + lane) * 2] = H;
    }
}

/* ---------------- stage loader: 24KB via cp.async (6 x 16B per thread) ----- */
__device__ __forceinline__ void stage_load(
    unsigned* smbuf, int st,
    const unsigned* __restrict__ Ah, const unsigned* __restrict__ Bh,
    size_t ablk, size_t bblk, int tid)
{
    unsigned d = smem_u32(smbuf + st * STAGE_UINTS) + tid * 16;
    const unsigned* a = Ah + ablk * 4096 + tid * 4;
    const unsigned* b = Bh + bblk * 2048 + tid * 4;
#pragma unroll
    for (int i = 0; i < 4; i++) CP16(d + i * 4096, a + i * 1024);
    CP16(d + 16384u, b);
    CP16(d + 20480u, b + 1024);
    CP_COMMIT();
}

/* ---------------- GEMM mainloop (CTA 256x128, Kblk 32, 4 stages) ----------- */
__device__ __forceinline__ void gemm_loop(
    unsigned* smbuf,
    const unsigned* __restrict__ Ah, const unsigned* __restrict__ Bh,
    size_t ablk0, size_t bblk0, int KB,
    float acc[4][8][4], int tid)
{
    const int lane = tid & 31, wid = tid >> 5;
    const int wm = wid >> 1, wn = wid & 1;

#pragma unroll
    for (int s = 0; s < 3; s++)
        stage_load(smbuf, s, Ah, Bh, ablk0 + s, bblk0 + s, tid);

    for (int kb = 0; kb < KB; kb++) {
        const int st = kb & 3;
        if (kb + 2 < KB) {
            asm volatile("cp.async.wait_group 2;" ::: "memory");
        } else {
            asm volatile("cp.async.wait_group 0;" ::: "memory");
        }
        __syncthreads();        /* stage kb ready; all warps done with kb-1 */
        const unsigned* sA = smbuf + st * STAGE_UINTS;
        const unsigned* sB = sA + 4096;
#pragma unroll
        for (int ki = 0; ki < 2; ki++) {
            const unsigned* pa = sA + ((ki * 16 + wm * 4) * 32 + lane) * 4;
            const unsigned* pb = sB + ((ki * 16 + wn * 8) * 32 + lane) * 2;
            uint4 ah[4];
            uint2 bh[8];
#pragma unroll
            for (int i = 0; i < 4; i++) ah[i] = *(const uint4*)(pa + i * 128);
#pragma unroll
            for (int j = 0; j < 8; j++) bh[j] = *(const uint2*)(pb + j * 64);
#pragma unroll
            for (int i = 0; i < 4; i++)
#pragma unroll
                for (int j = 0; j < 8; j++) mma16816(acc[i][j], ah[i], bh[j]);
        }
        if (kb + 3 < KB)
            stage_load(smbuf, (kb + 3) & 3, Ah, Bh, ablk0 + kb + 3, bblk0 + kb + 3, tid);
    }
}

__device__ __forceinline__ int resolve_expert(int p0) {
    int e = -1;
    if (p0 < g_segbase[NE]) {
#pragma unroll
        for (int i = NE - 1; i >= 0; i--)
            if (p0 >= g_segbase[i]) { e = i; break; }
    }
    return e;
}

/* ---------------- GEMM1: h = relu(X W1^T + b1) -> fp16 A-layout ------------- */
__global__ __launch_bounds__(256, 1)
void k_gemm1(const float* __restrict__ b1) {
    __shared__ int s_e;
    extern __shared__ unsigned smbuf[];
    const int tid = threadIdx.x;
    const int nt = blockIdx.x, mt = blockIdx.y;

    if (tid == 0) s_e = resolve_expert(mt * 256);
    __syncthreads();
    const int e = s_e;
    if (e < 0) return;

    float acc[4][8][4];
#pragma unroll
    for (int i = 0; i < 4; i++)
#pragma unroll
        for (int j = 0; j < 8; j++)
#pragma unroll
            for (int c = 0; c < 4; c++) acc[i][j][c] = 0.f;

    gemm_loop(smbuf, g_xh, g_w1h,
              (size_t)mt * KB1, ((size_t)e * NT1 + nt) * KB1, KB1, acc, tid);

    /* epilogue: bias+relu, fp16 convert, write h in A-layout (C-frag == A-frag) */
    const int lane = tid & 31, wid = tid >> 5;
    const int wm = wid >> 1, wn = wid & 1;
    const int tig = lane & 3;
    const float* bias = b1 + (size_t)e * HDIM + nt * 128 + wn * 64 + 2 * tig;
#pragma unroll
    for (int mi = 0; mi < 4; mi++) {
        const int mig = wm * 4 + mi;
#pragma unroll
        for (int jp = 0; jp < 4; jp++) {
            float2 b0 = *(const float2*)(bias + (2 * jp) * 8);
            float2 b1v = *(const float2*)(bias + (2 * jp + 1) * 8);
            const float* c0 = acc[mi][2 * jp];
            const float* c1 = acc[mi][2 * jp + 1];
            uint4 H;
            H.x = pack2(fmaxf(c0[0] + b0.x, 0.f),  fmaxf(c0[1] + b0.y, 0.f));
            H.y = pack2(fmaxf(c0[2] + b0.x, 0.f),  fmaxf(c0[3] + b0.y, 0.f));
            H.z = pack2(fmaxf(c1[0] + b1v.x, 0.f), fmaxf(c1[1] + b1v.y, 0.f));
            H.w = pack2(fmaxf(c1[2] + b1v.x, 0.f), fmaxf(c1[3] + b1v.y, 0.f));
            const int hcol0 = nt * 128 + wn * 64 + jp * 16;
            const size_t base = ((size_t)mt * KB2 + (hcol0 >> 5)) * 4096
                + ((size_t)(((hcol0 >> 4) & 1) * 16 + mig) * 32 + lane) * 4;
            *(uint4*)&g_hh[base] = H;
        }
    }
}

/* ---------------- GEMM2: y_slot = w * (h W2^T + b2), plain stores ----------- */
__global__ __launch_bounds__(256, 1)
void k_gemm2(const float* __restrict__ b2) {
    __shared__ int s_e;
    __shared__ int stok[256];
    __shared__ float swgt[256];
    extern __shared__ unsigned smbuf[];
    const int tid = threadIdx.x;
    const int nt = blockIdx.x, mt = blockIdx.y;

    if (tid == 0) s_e = resolve_expert(mt * 256);
    __syncthreads();
    const int e = s_e;
    if (e < 0) return;

    stok[tid] = g_tok[mt * 256 + tid];
    swgt[tid] = g_wgt[mt * 256 + tid];

    float acc[4][8][4];
#pragma unroll
    for (int i = 0; i < 4; i++)
#pragma unroll
        for (int j = 0; j < 8; j++)
#pragma unroll
            for (int c = 0; c < 4; c++) acc[i][j][c] = 0.f;

    gemm_loop(smbuf, g_hh, g_w2h,
              (size_t)mt * KB2, ((size_t)e * NT2 + nt) * KB2, KB2, acc, tid);

    const int lane = tid & 31, wid = tid >> 5;
    const int wm = wid >> 1, wn = wid & 1;
    const int g = lane >> 2, tig = lane & 3;
#pragma unroll
    for (int mi = 0; mi < 4; mi++) {
        const int r0 = wm * 64 + mi * 16 + g;
        const int t0 = stok[r0], t1 = stok[r0 + 8];
        const float w0 = swgt[r0], w1 = swgt[r0 + 8];
        float* y0 = g_y + (size_t)(mt * 256 + r0) * DOUT;
        float* y1 = y0 + (size_t)8 * DOUT;
#pragma unroll
        for (int j = 0; j < 8; j++) {
            const int col = nt * 128 + wn * 64 + j * 8 + 2 * tig;
            float2 bb = *(const float2*)&b2[(size_t)e * DOUT + col];
            if (t0 >= 0) {
                float2 v = make_float2(w0 * (acc[mi][j][0] + bb.x),
                                       w0 * (acc[mi][j][1] + bb.y));
                *(float2*)(y0 + col) = v;
            }
            if (t1 >= 0) {
                float2 v = make_float2(w1 * (acc[mi][j][2] + bb.x),
                                       w1 * (acc[mi][j][3] + bb.y));
                *(float2*)(y1 + col) = v;
            }
        }
    }
}

/* ---------------- combine: out[t] = y[slot0] + y[slot1] --------------------- */
__global__ void k_combine(float* __restrict__ out) {
    const int t = blockIdx.x;
    const int c = threadIdx.x;               /* 256 threads x float4 = 1024 */
    const int s0 = g_slot[2 * t], s1 = g_slot[2 * t + 1];
    const float4 a = ((const float4*)(g_y + (size_t)s0 * DOUT))[c];
    const float4 b = ((const float4*)(g_y + (size_t)s1 * DOUT))[c];
    ((float4*)(out + (size_t)t * DOUT))[c] =
        make_float4(a.x + b.x, a.y + b.y, a.z + b.z, a.w + b.w);
}

/* ---------------- launch ----------------------------------------------------- */
extern "C" void kernel_launch(void* const* d_in, const int* in_sizes, int n_in,
                              void* d_out, int out_size) {
    const float* x  = (const float*)d_in[0];
    const float* rW = (const float*)d_in[1];
    const float* rb = (const float*)d_in[2];
    const float* W1 = (const float*)d_in[3];
    const float* b1 = (const float*)d_in[4];
    const float* W2 = (const float*)d_in[5];
    const float* b2 = (const float*)d_in[6];
    float* out = (float*)d_out;

    float* probs;
    if (out_size >= (int)(BQ * DOUT + BQ * NE)) {
        probs = out + (size_t)BQ * DOUT;
    } else {
        void* p = nullptr;
        cudaGetSymbolAddress(&p, g_probs_scratch);
        probs = (float*)p;
    }

    /* resolve DEVICE addresses for scratch passed as kernel args (ATS trap!) */
    void *p_w1h = nullptr, *p_w2h = nullptr;
    cudaGetSymbolAddress(&p_w1h, g_w1h);
    cudaGetSymbolAddress(&p_w2h, g_w2h);

    cudaFuncSetAttribute(k_gemm1, cudaFuncAttributeMaxDynamicSharedMemorySize, DSMEM_BYTES);
    cudaFuncSetAttribute(k_gemm2, cudaFuncAttributeMaxDynamicSharedMemorySize, DSMEM_BYTES);

    k_init<<<(PADM + 255) / 256, 256>>>();
    k_router<<<BQ, 128>>>(x, rW, rb, probs);
    k_prefix<<<1, 1>>>();
    k_scatter<<<NA / 256, 256>>>();
    k_xsplit<<<dim3(KB1, MT), 512>>>(x);
    k_wsplit<<<dim3(KB1, NT1, NE), 512>>>(W1, (unsigned*)p_w1h, DIN);
    k_wsplit<<<dim3(KB2, NT2, NE), 512>>>(W2, (unsigned*)p_w2h, HDIM);
    k_gemm1<<<dim3(NT1, MT), 256, DSMEM_BYTES>>>(b1);
    k_gemm2<<<dim3(NT2, MT), 256, DSMEM_BYTES>>>(b2);
    k_combine<<<BQ, 256>>>(out);
    (void)in_sizes; (void)n_in;
}